// round 2
// baseline (speedup 1.0000x reference)
#include <cuda_runtime.h>
#include <cuda_bf16.h>
#include <math.h>

// Problem constants
#define N_HEADS 32
#define N_KV 8
#define HDIM 128
#define DIM 4096
#define BS 32
#define MAXSEQ 2048
#define KSPLIT 8
#define NSPLIT 4   // KV splits for attention

// ---------------- device scratch (static, allocation-free) ----------------
__device__ float g_qkv_part[KSPLIT][BS][6144];   // partial QKV projections
__device__ float g_q[BS * 4096];                 // rope'd q
__device__ float g_knew[BS * 1024];              // rope'd new k (per kv head)
__device__ float g_vnew[BS * 1024];              // new v
__device__ float g_po[BS * N_HEADS * NSPLIT * HDIM]; // split attention partial outputs
__device__ float g_pm[BS * N_HEADS * NSPLIT];
__device__ float g_pl[BS * N_HEADS * NSPLIT];
__device__ float g_attn[BS * 4096];              // attention output (pre-WO)
__device__ float g_wo_part[KSPLIT][BS * 4096];   // partial WO projections

// ---------------- QKV GEMM: [32,4096] @ concat(wq,wk,wv) -> partials -----
// grid (24 col-blocks, 8 k-splits), block 128. Each thread: 2 adjacent cols,
// all 32 batches in registers; x chunk staged in smem (broadcast reads).
__global__ void __launch_bounds__(128)
gemm_qkv_kernel(const float* __restrict__ x,
                const float* __restrict__ wq,
                const float* __restrict__ wk,
                const float* __restrict__ wv) {
    __shared__ float xs[32 * 256];
    int tid = threadIdx.x;
    int gcol = (blockIdx.x * 128 + tid) * 2;     // 0..6142, even
    const float* w; int ldw, c;
    if (gcol < 4096)      { w = wq; ldw = 4096; c = gcol; }
    else if (gcol < 5120) { w = wk; ldw = 1024; c = gcol - 4096; }
    else                  { w = wv; ldw = 1024; c = gcol - 5120; }
    int kbase = blockIdx.y * 512;

    float acc0[32], acc1[32];
#pragma unroll
    for (int b = 0; b < 32; b++) { acc0[b] = 0.f; acc1[b] = 0.f; }

    for (int kc = 0; kc < 512; kc += 256) {
        const float4* x4 = (const float4*)x;
        float4* xs4 = (float4*)xs;
        for (int u = tid; u < 32 * 64; u += 128) {
            int b = u >> 6, k4 = u & 63;
            xs4[b * 64 + k4] = x4[b * 1024 + ((kbase + kc) >> 2) + k4];
        }
        __syncthreads();
        const float* wp = w + (size_t)(kbase + kc) * ldw + c;
#pragma unroll 2
        for (int k = 0; k < 256; k++) {
            float2 wv2 = *(const float2*)(wp + (size_t)k * ldw);
#pragma unroll
            for (int b = 0; b < 32; b++) {
                float xv = xs[b * 256 + k];          // warp-broadcast LDS
                acc0[b] = fmaf(wv2.x, xv, acc0[b]);
                acc1[b] = fmaf(wv2.y, xv, acc1[b]);
            }
        }
        __syncthreads();
    }
    float* out = &g_qkv_part[blockIdx.y][0][0];
#pragma unroll
    for (int b = 0; b < 32; b++) {
        float2 v2 = make_float2(acc0[b], acc1[b]);
        *(float2*)&out[b * 6144 + gcol] = v2;
    }
}

// ---------------- reduce K-split partials + RoPE -------------------------
// One thread per element pair. q -> g_q, k -> g_knew (rope'd), v -> g_vnew.
__global__ void rope_combine_kernel(const float* __restrict__ fc,
                                    const float* __restrict__ fs) {
    int idx = blockIdx.x * blockDim.x + threadIdx.x;   // 0..98303
    if (idx >= 32 * 3072) return;
    int b = idx / 3072;
    int col = (idx % 3072) * 2;
    float s0 = 0.f, s1 = 0.f;
#pragma unroll
    for (int p = 0; p < KSPLIT; p++) {
        s0 += g_qkv_part[p][b][col];
        s1 += g_qkv_part[p][b][col + 1];
    }
    if (col < 4096) {
        int i = (col & 127) >> 1;
        float cc = fc[i], ss = fs[i];
        g_q[b * 4096 + col]     = s0 * cc - s1 * ss;
        g_q[b * 4096 + col + 1] = s0 * ss + s1 * cc;
    } else if (col < 5120) {
        int kc = col - 4096;
        int i = (kc & 127) >> 1;
        float cc = fc[i], ss = fs[i];
        g_knew[b * 1024 + kc]     = s0 * cc - s1 * ss;
        g_knew[b * 1024 + kc + 1] = s0 * ss + s1 * cc;
    } else {
        int vc = col - 5120;
        g_vnew[b * 1024 + vc]     = s0;
        g_vnew[b * 1024 + vc + 1] = s1;
    }
}

// ---------------- split-KV attention -------------------------------------
// grid (8 kv-heads, 4 splits, 32 batches), block 256 (8 warps).
// 4 query heads share each K/V read (GQA). Position L-1 reads g_knew/g_vnew.
__global__ void __launch_bounds__(256)
attn_split_kernel(const float* __restrict__ cache_k,
                  const float* __restrict__ cache_v,
                  const int* __restrict__ sp) {
    __shared__ float qs[4 * 128];
    __shared__ float sc[4][512];
    __shared__ float vt[32 * 128];
    __shared__ float sm_m[4], sm_l[4];

    int g = blockIdx.x, split = blockIdx.y, b = blockIdx.z;
    int tid = threadIdx.x, lane = tid & 31, w = tid >> 5;
    int L = sp ? (sp[0] + 1) : MAXSEQ;
    int chunk = (L + NSPLIT - 1) / NSPLIT;
    int t0 = split * chunk;
    int cnt = L - t0;
    if (cnt > chunk) cnt = chunk;
    if (cnt < 0) cnt = 0;

    for (int u = tid; u < 512; u += 256)
        qs[u] = g_q[b * 4096 + g * 512 + u];
    __syncthreads();

    float4 qr[4];
#pragma unroll
    for (int h = 0; h < 4; h++) qr[h] = ((const float4*)qs)[h * 32 + lane];

    const float scale = 0.08838834764831845f;  // 1/sqrt(128)

    // ---- scores: one warp per key position, coalesced 512B K loads ----
    for (int ti = w; ti < cnt; ti += 8) {
        int t = t0 + ti;
        const float4* kp = (t == L - 1)
            ? (const float4*)(g_knew + b * 1024 + g * 128)
            : (const float4*)(cache_k + (((size_t)b * MAXSEQ + t) * N_KV + g) * HDIM);
        float4 kv = kp[lane];
        float a0 = qr[0].x*kv.x + qr[0].y*kv.y + qr[0].z*kv.z + qr[0].w*kv.w;
        float a1 = qr[1].x*kv.x + qr[1].y*kv.y + qr[1].z*kv.z + qr[1].w*kv.w;
        float a2 = qr[2].x*kv.x + qr[2].y*kv.y + qr[2].z*kv.z + qr[2].w*kv.w;
        float a3 = qr[3].x*kv.x + qr[3].y*kv.y + qr[3].z*kv.z + qr[3].w*kv.w;
#pragma unroll
        for (int off = 16; off; off >>= 1) {
            a0 += __shfl_xor_sync(~0u, a0, off);
            a1 += __shfl_xor_sync(~0u, a1, off);
            a2 += __shfl_xor_sync(~0u, a2, off);
            a3 += __shfl_xor_sync(~0u, a3, off);
        }
        if (lane == 0) {
            sc[0][ti] = a0 * scale; sc[1][ti] = a1 * scale;
            sc[2][ti] = a2 * scale; sc[3][ti] = a3 * scale;
        }
    }
    __syncthreads();

    // ---- softmax stats (one warp per head) ----
    if (w < 4) {
        float m = -1e30f;
        for (int ti = lane; ti < cnt; ti += 32) m = fmaxf(m, sc[w][ti]);
#pragma unroll
        for (int off = 16; off; off >>= 1) m = fmaxf(m, __shfl_xor_sync(~0u, m, off));
        float l = 0.f;
        for (int ti = lane; ti < cnt; ti += 32) {
            float e = __expf(sc[w][ti] - m);
            sc[w][ti] = e;
            l += e;
        }
#pragma unroll
        for (int off = 16; off; off >>= 1) l += __shfl_xor_sync(~0u, l, off);
        if (lane == 0) { sm_m[w] = m; sm_l[w] = l; }
    }
    __syncthreads();

    // ---- PV: smem-tiled V, each thread owns (h, d) and (h+2, d) ----
    int h0 = tid >> 7;        // 0..1
    int d0 = tid & 127;
    int h1 = h0 + 2;
    float acc0 = 0.f, acc1 = 0.f;
    for (int tb = 0; tb < cnt; tb += 32) {
        int nt = cnt - tb; if (nt > 32) nt = 32;
        for (int u = tid; u < nt * 32; u += 256) {
            int r = u >> 5, c4 = u & 31;
            int t = t0 + tb + r;
            const float4* vp = (t == L - 1)
                ? (const float4*)(g_vnew + b * 1024 + g * 128)
                : (const float4*)(cache_v + (((size_t)b * MAXSEQ + t) * N_KV + g) * HDIM);
            ((float4*)vt)[r * 32 + c4] = vp[c4];
        }
        __syncthreads();
        for (int j = 0; j < nt; j++) {
            float vv = vt[j * 128 + d0];
            acc0 = fmaf(sc[h0][tb + j], vv, acc0);
            acc1 = fmaf(sc[h1][tb + j], vv, acc1);
        }
        __syncthreads();
    }

    int hh0 = g * 4 + h0, hh1 = g * 4 + h1;
    g_po[((b * N_HEADS + hh0) * NSPLIT + split) * HDIM + d0] = acc0;
    g_po[((b * N_HEADS + hh1) * NSPLIT + split) * HDIM + d0] = acc1;
    if (d0 == 0) {
        g_pm[(b * N_HEADS + hh0) * NSPLIT + split] = sm_m[h0];
        g_pl[(b * N_HEADS + hh0) * NSPLIT + split] = sm_l[h0];
        g_pm[(b * N_HEADS + hh1) * NSPLIT + split] = sm_m[h1];
        g_pl[(b * N_HEADS + hh1) * NSPLIT + split] = sm_l[h1];
    }
}

// ---------------- combine attention splits (log-sum-exp) -----------------
__global__ void combine_attn_kernel() {
    int h = blockIdx.x, b = blockIdx.y, d = threadIdx.x;
    int base = (b * N_HEADS + h) * NSPLIT;
    float m0 = g_pm[base], m1 = g_pm[base+1], m2 = g_pm[base+2], m3 = g_pm[base+3];
    float M = fmaxf(fmaxf(m0, m1), fmaxf(m2, m3));
    float w0 = __expf(m0 - M), w1 = __expf(m1 - M);
    float w2 = __expf(m2 - M), w3 = __expf(m3 - M);
    float denom = w0 * g_pl[base] + w1 * g_pl[base+1] + w2 * g_pl[base+2] + w3 * g_pl[base+3];
    float o = w0 * g_po[(base+0) * HDIM + d] + w1 * g_po[(base+1) * HDIM + d]
            + w2 * g_po[(base+2) * HDIM + d] + w3 * g_po[(base+3) * HDIM + d];
    g_attn[b * 4096 + h * HDIM + d] = o / denom;
}

// ---------------- WO GEMM: g_attn[32,4096] @ wo[4096,4096] ---------------
__global__ void __launch_bounds__(128)
gemm_wo_kernel(const float* __restrict__ wo) {
    __shared__ float xs[32 * 256];
    int tid = threadIdx.x;
    int c = (blockIdx.x * 128 + tid) * 2;   // 0..4094
    int kbase = blockIdx.y * 512;

    float acc0[32], acc1[32];
#pragma unroll
    for (int b = 0; b < 32; b++) { acc0[b] = 0.f; acc1[b] = 0.f; }

    for (int kc = 0; kc < 512; kc += 256) {
        const float4* x4 = (const float4*)g_attn;
        float4* xs4 = (float4*)xs;
        for (int u = tid; u < 32 * 64; u += 128) {
            int b = u >> 6, k4 = u & 63;
            xs4[b * 64 + k4] = x4[b * 1024 + ((kbase + kc) >> 2) + k4];
        }
        __syncthreads();
        const float* wp = wo + (size_t)(kbase + kc) * 4096 + c;
#pragma unroll 2
        for (int k = 0; k < 256; k++) {
            float2 wv2 = *(const float2*)(wp + (size_t)k * 4096);
#pragma unroll
            for (int b = 0; b < 32; b++) {
                float xv = xs[b * 256 + k];
                acc0[b] = fmaf(wv2.x, xv, acc0[b]);
                acc1[b] = fmaf(wv2.y, xv, acc1[b]);
            }
        }
        __syncthreads();
    }
    float* out = g_wo_part[blockIdx.y];
#pragma unroll
    for (int b = 0; b < 32; b++) {
        float2 v2 = make_float2(acc0[b], acc1[b]);
        *(float2*)&out[b * 4096 + c] = v2;
    }
}

// ---------------- sum WO partials into d_out -----------------------------
__global__ void final_sum_kernel(float* __restrict__ out) {
    int idx = blockIdx.x * blockDim.x + threadIdx.x;   // 0..131071
    float s = 0.f;
#pragma unroll
    for (int p = 0; p < KSPLIT; p++) s += g_wo_part[p][idx];
    out[idx] = s;
}

// ---------------- launch -------------------------------------------------
extern "C" void kernel_launch(void* const* d_in, const int* in_sizes, int n_in,
                              void* d_out, int out_size) {
    const float* x  = (const float*)d_in[0];
    const float* wq = (const float*)d_in[1];
    const float* wk = (const float*)d_in[2];
    const float* wv = (const float*)d_in[3];
    const float* wo = (const float*)d_in[4];
    const float* ck = (const float*)d_in[5];
    const float* cv = (const float*)d_in[6];
    const float* fc = (const float*)d_in[7];
    const float* fs = (const float*)d_in[8];
    const int*   sp = (n_in > 9) ? (const int*)d_in[9] : nullptr;

    gemm_qkv_kernel<<<dim3(24, KSPLIT), 128>>>(x, wq, wk, wv);
    rope_combine_kernel<<<384, 256>>>(fc, fs);
    attn_split_kernel<<<dim3(N_KV, NSPLIT, BS), 256>>>(ck, cv, sp);
    combine_attn_kernel<<<dim3(N_HEADS, BS), 128>>>();
    gemm_wo_kernel<<<dim3(16, KSPLIT), 128>>>(wo);
    final_sum_kernel<<<512, 256>>>((float*)d_out);
}

// round 3
// speedup vs baseline: 2.0296x; 2.0296x over previous
#include <cuda_runtime.h>
#include <cuda_bf16.h>
#include <math.h>

// Problem constants
#define N_HEADS 32
#define N_KV 8
#define HDIM 128
#define DIM 4096
#define BS 32
#define MAXSEQ 2048
#define KSPLIT 32
#define NSPLIT 4   // KV splits for attention

// ---------------- device scratch (static, allocation-free) ----------------
__device__ float g_qkv_part[KSPLIT][BS][6144];   // partial QKV projections
__device__ float g_q[BS * 4096];                 // rope'd q
__device__ float g_knew[BS * 1024];              // rope'd new k (per kv head)
__device__ float g_vnew[BS * 1024];              // new v
__device__ float g_po[BS * N_HEADS * NSPLIT * HDIM]; // split attention partial outputs
__device__ float g_pm[BS * N_HEADS * NSPLIT];
__device__ float g_pl[BS * N_HEADS * NSPLIT];
__device__ float g_attn[BS * 4096];              // attention output (pre-WO)
__device__ float g_wo_part[KSPLIT][BS * 4096];   // partial WO projections

#define XPAD 36   // smem row pitch for xs[k][b] (float4-aligned, conflict-free)

// ---------------- QKV GEMM: [32,4096] @ concat(wq,wk,wv) -> partials -----
// grid (24 col-blocks, 32 k-splits), block 128. Each thread: 2 adjacent cols,
// all 32 batches in registers. x chunk staged TRANSPOSED in smem -> inner
// loop reads x via broadcast LDS.128 (8 LDS per 64 FMA). Weights prefetched
// 8-deep (MLP=8) to cover DRAM latency.
__global__ void __launch_bounds__(128)
gemm_qkv_kernel(const float* __restrict__ x,
                const float* __restrict__ wq,
                const float* __restrict__ wk,
                const float* __restrict__ wv) {
    __shared__ float xs[128 * XPAD];   // xs[k][b], k in 0..127, b in 0..31
    int tid = threadIdx.x;
    int gcol = (blockIdx.x * 128 + tid) * 2;     // 0..6142, even
    const float* w; int ldw, c;
    if (gcol < 4096)      { w = wq; ldw = 4096; c = gcol; }
    else if (gcol < 5120) { w = wk; ldw = 1024; c = gcol - 4096; }
    else                  { w = wv; ldw = 1024; c = gcol - 5120; }
    int kbase = blockIdx.y * 128;

    // stage x[b][kbase..kbase+127] -> xs[k][b]
    {
        const float4* x4 = (const float4*)x;
        for (int u = tid; u < 32 * 32; u += 128) {
            int b = u & 31, k4 = u >> 5;
            float4 v = x4[b * 1024 + (kbase >> 2) + k4];
            xs[(k4 * 4 + 0) * XPAD + b] = v.x;
            xs[(k4 * 4 + 1) * XPAD + b] = v.y;
            xs[(k4 * 4 + 2) * XPAD + b] = v.z;
            xs[(k4 * 4 + 3) * XPAD + b] = v.w;
        }
    }
    __syncthreads();

    float acc0[32], acc1[32];
#pragma unroll
    for (int b = 0; b < 32; b++) { acc0[b] = 0.f; acc1[b] = 0.f; }

    const float* wp = w + (size_t)kbase * ldw + c;
    for (int kk = 0; kk < 128; kk += 8) {
        float2 wr[8];
#pragma unroll
        for (int j = 0; j < 8; j++)
            wr[j] = *(const float2*)(wp + (size_t)(kk + j) * ldw);
#pragma unroll
        for (int j = 0; j < 8; j++) {
            const float4* xrow = (const float4*)(xs + (kk + j) * XPAD);
#pragma unroll
            for (int b4 = 0; b4 < 8; b4++) {
                float4 xv = xrow[b4];           // broadcast LDS.128
                acc0[b4*4+0] = fmaf(wr[j].x, xv.x, acc0[b4*4+0]);
                acc0[b4*4+1] = fmaf(wr[j].x, xv.y, acc0[b4*4+1]);
                acc0[b4*4+2] = fmaf(wr[j].x, xv.z, acc0[b4*4+2]);
                acc0[b4*4+3] = fmaf(wr[j].x, xv.w, acc0[b4*4+3]);
                acc1[b4*4+0] = fmaf(wr[j].y, xv.x, acc1[b4*4+0]);
                acc1[b4*4+1] = fmaf(wr[j].y, xv.y, acc1[b4*4+1]);
                acc1[b4*4+2] = fmaf(wr[j].y, xv.z, acc1[b4*4+2]);
                acc1[b4*4+3] = fmaf(wr[j].y, xv.w, acc1[b4*4+3]);
            }
        }
    }
    float* out = &g_qkv_part[blockIdx.y][0][0];
#pragma unroll
    for (int b = 0; b < 32; b++) {
        float2 v2 = make_float2(acc0[b], acc1[b]);
        *(float2*)&out[b * 6144 + gcol] = v2;
    }
}

// ---------------- reduce K-split partials + RoPE -------------------------
__global__ void rope_combine_kernel(const float* __restrict__ fc,
                                    const float* __restrict__ fs) {
    int idx = blockIdx.x * blockDim.x + threadIdx.x;   // 0..98303
    if (idx >= 32 * 3072) return;
    int b = idx / 3072;
    int col = (idx % 3072) * 2;
    float s0 = 0.f, s1 = 0.f;
#pragma unroll
    for (int p = 0; p < KSPLIT; p++) {
        s0 += g_qkv_part[p][b][col];
        s1 += g_qkv_part[p][b][col + 1];
    }
    if (col < 4096) {
        int i = (col & 127) >> 1;
        float cc = fc[i], ss = fs[i];
        g_q[b * 4096 + col]     = s0 * cc - s1 * ss;
        g_q[b * 4096 + col + 1] = s0 * ss + s1 * cc;
    } else if (col < 5120) {
        int kc = col - 4096;
        int i = (kc & 127) >> 1;
        float cc = fc[i], ss = fs[i];
        g_knew[b * 1024 + kc]     = s0 * cc - s1 * ss;
        g_knew[b * 1024 + kc + 1] = s0 * ss + s1 * cc;
    } else {
        int vc = col - 5120;
        g_vnew[b * 1024 + vc]     = s0;
        g_vnew[b * 1024 + vc + 1] = s1;
    }
}

// ---------------- split-KV attention -------------------------------------
__global__ void __launch_bounds__(256)
attn_split_kernel(const float* __restrict__ cache_k,
                  const float* __restrict__ cache_v,
                  const int* __restrict__ sp) {
    __shared__ float qs[4 * 128];
    __shared__ float sc[4][512];
    __shared__ float vt[32 * 128];
    __shared__ float sm_m[4], sm_l[4];

    int g = blockIdx.x, split = blockIdx.y, b = blockIdx.z;
    int tid = threadIdx.x, lane = tid & 31, w = tid >> 5;
    int L = sp ? (sp[0] + 1) : MAXSEQ;
    int chunk = (L + NSPLIT - 1) / NSPLIT;
    int t0 = split * chunk;
    int cnt = L - t0;
    if (cnt > chunk) cnt = chunk;
    if (cnt < 0) cnt = 0;

    for (int u = tid; u < 512; u += 256)
        qs[u] = g_q[b * 4096 + g * 512 + u];
    __syncthreads();

    float4 qr[4];
#pragma unroll
    for (int h = 0; h < 4; h++) qr[h] = ((const float4*)qs)[h * 32 + lane];

    const float scale = 0.08838834764831845f;  // 1/sqrt(128)

    // ---- scores: one warp per key position, coalesced 512B K loads ----
    for (int ti = w; ti < cnt; ti += 8) {
        int t = t0 + ti;
        const float4* kp = (t == L - 1)
            ? (const float4*)(g_knew + b * 1024 + g * 128)
            : (const float4*)(cache_k + (((size_t)b * MAXSEQ + t) * N_KV + g) * HDIM);
        float4 kv = kp[lane];
        float a0 = qr[0].x*kv.x + qr[0].y*kv.y + qr[0].z*kv.z + qr[0].w*kv.w;
        float a1 = qr[1].x*kv.x + qr[1].y*kv.y + qr[1].z*kv.z + qr[1].w*kv.w;
        float a2 = qr[2].x*kv.x + qr[2].y*kv.y + qr[2].z*kv.z + qr[2].w*kv.w;
        float a3 = qr[3].x*kv.x + qr[3].y*kv.y + qr[3].z*kv.z + qr[3].w*kv.w;
#pragma unroll
        for (int off = 16; off; off >>= 1) {
            a0 += __shfl_xor_sync(~0u, a0, off);
            a1 += __shfl_xor_sync(~0u, a1, off);
            a2 += __shfl_xor_sync(~0u, a2, off);
            a3 += __shfl_xor_sync(~0u, a3, off);
        }
        if (lane == 0) {
            sc[0][ti] = a0 * scale; sc[1][ti] = a1 * scale;
            sc[2][ti] = a2 * scale; sc[3][ti] = a3 * scale;
        }
    }
    __syncthreads();

    // ---- softmax stats (one warp per head) ----
    if (w < 4) {
        float m = -1e30f;
        for (int ti = lane; ti < cnt; ti += 32) m = fmaxf(m, sc[w][ti]);
#pragma unroll
        for (int off = 16; off; off >>= 1) m = fmaxf(m, __shfl_xor_sync(~0u, m, off));
        float l = 0.f;
        for (int ti = lane; ti < cnt; ti += 32) {
            float e = __expf(sc[w][ti] - m);
            sc[w][ti] = e;
            l += e;
        }
#pragma unroll
        for (int off = 16; off; off >>= 1) l += __shfl_xor_sync(~0u, l, off);
        if (lane == 0) { sm_m[w] = m; sm_l[w] = l; }
    }
    __syncthreads();

    // ---- PV: smem-tiled V, each thread owns (h, d) and (h+2, d) ----
    int h0 = tid >> 7;        // 0..1
    int d0 = tid & 127;
    int h1 = h0 + 2;
    float acc0 = 0.f, acc1 = 0.f;
    for (int tb = 0; tb < cnt; tb += 32) {
        int nt = cnt - tb; if (nt > 32) nt = 32;
        for (int u = tid; u < nt * 32; u += 256) {
            int r = u >> 5, c4 = u & 31;
            int t = t0 + tb + r;
            const float4* vp = (t == L - 1)
                ? (const float4*)(g_vnew + b * 1024 + g * 128)
                : (const float4*)(cache_v + (((size_t)b * MAXSEQ + t) * N_KV + g) * HDIM);
            ((float4*)vt)[r * 32 + c4] = vp[c4];
        }
        __syncthreads();
        for (int j = 0; j < nt; j++) {
            float vv = vt[j * 128 + d0];
            acc0 = fmaf(sc[h0][tb + j], vv, acc0);
            acc1 = fmaf(sc[h1][tb + j], vv, acc1);
        }
        __syncthreads();
    }

    int hh0 = g * 4 + h0, hh1 = g * 4 + h1;
    g_po[((b * N_HEADS + hh0) * NSPLIT + split) * HDIM + d0] = acc0;
    g_po[((b * N_HEADS + hh1) * NSPLIT + split) * HDIM + d0] = acc1;
    if (d0 == 0) {
        g_pm[(b * N_HEADS + hh0) * NSPLIT + split] = sm_m[h0];
        g_pl[(b * N_HEADS + hh0) * NSPLIT + split] = sm_l[h0];
        g_pm[(b * N_HEADS + hh1) * NSPLIT + split] = sm_m[h1];
        g_pl[(b * N_HEADS + hh1) * NSPLIT + split] = sm_l[h1];
    }
}

// ---------------- combine attention splits (log-sum-exp) -----------------
__global__ void combine_attn_kernel() {
    int h = blockIdx.x, b = blockIdx.y, d = threadIdx.x;
    int base = (b * N_HEADS + h) * NSPLIT;
    float m0 = g_pm[base], m1 = g_pm[base+1], m2 = g_pm[base+2], m3 = g_pm[base+3];
    float M = fmaxf(fmaxf(m0, m1), fmaxf(m2, m3));
    float w0 = __expf(m0 - M), w1 = __expf(m1 - M);
    float w2 = __expf(m2 - M), w3 = __expf(m3 - M);
    float denom = w0 * g_pl[base] + w1 * g_pl[base+1] + w2 * g_pl[base+2] + w3 * g_pl[base+3];
    float o = w0 * g_po[(base+0) * HDIM + d] + w1 * g_po[(base+1) * HDIM + d]
            + w2 * g_po[(base+2) * HDIM + d] + w3 * g_po[(base+3) * HDIM + d];
    g_attn[b * 4096 + h * HDIM + d] = o / denom;
}

// ---------------- WO GEMM: g_attn[32,4096] @ wo[4096,4096] ---------------
__global__ void __launch_bounds__(128)
gemm_wo_kernel(const float* __restrict__ wo) {
    __shared__ float xs[128 * XPAD];
    int tid = threadIdx.x;
    int c = (blockIdx.x * 128 + tid) * 2;   // 0..4094
    int kbase = blockIdx.y * 128;

    {
        const float4* x4 = (const float4*)g_attn;
        for (int u = tid; u < 32 * 32; u += 128) {
            int b = u & 31, k4 = u >> 5;
            float4 v = x4[b * 1024 + (kbase >> 2) + k4];
            xs[(k4 * 4 + 0) * XPAD + b] = v.x;
            xs[(k4 * 4 + 1) * XPAD + b] = v.y;
            xs[(k4 * 4 + 2) * XPAD + b] = v.z;
            xs[(k4 * 4 + 3) * XPAD + b] = v.w;
        }
    }
    __syncthreads();

    float acc0[32], acc1[32];
#pragma unroll
    for (int b = 0; b < 32; b++) { acc0[b] = 0.f; acc1[b] = 0.f; }

    const float* wp = wo + (size_t)kbase * 4096 + c;
    for (int kk = 0; kk < 128; kk += 8) {
        float2 wr[8];
#pragma unroll
        for (int j = 0; j < 8; j++)
            wr[j] = *(const float2*)(wp + (size_t)(kk + j) * 4096);
#pragma unroll
        for (int j = 0; j < 8; j++) {
            const float4* xrow = (const float4*)(xs + (kk + j) * XPAD);
#pragma unroll
            for (int b4 = 0; b4 < 8; b4++) {
                float4 xv = xrow[b4];
                acc0[b4*4+0] = fmaf(wr[j].x, xv.x, acc0[b4*4+0]);
                acc0[b4*4+1] = fmaf(wr[j].x, xv.y, acc0[b4*4+1]);
                acc0[b4*4+2] = fmaf(wr[j].x, xv.z, acc0[b4*4+2]);
                acc0[b4*4+3] = fmaf(wr[j].x, xv.w, acc0[b4*4+3]);
                acc1[b4*4+0] = fmaf(wr[j].y, xv.x, acc1[b4*4+0]);
                acc1[b4*4+1] = fmaf(wr[j].y, xv.y, acc1[b4*4+1]);
                acc1[b4*4+2] = fmaf(wr[j].y, xv.z, acc1[b4*4+2]);
                acc1[b4*4+3] = fmaf(wr[j].y, xv.w, acc1[b4*4+3]);
            }
        }
    }
    float* out = g_wo_part[blockIdx.y];
#pragma unroll
    for (int b = 0; b < 32; b++) {
        float2 v2 = make_float2(acc0[b], acc1[b]);
        *(float2*)&out[b * 4096 + c] = v2;
    }
}

// ---------------- sum WO partials into d_out -----------------------------
__global__ void final_sum_kernel(float* __restrict__ out) {
    int idx = blockIdx.x * blockDim.x + threadIdx.x;   // 0..131071
    float s = 0.f;
#pragma unroll
    for (int p = 0; p < KSPLIT; p++) s += g_wo_part[p][idx];
    out[idx] = s;
}

// ---------------- launch -------------------------------------------------
extern "C" void kernel_launch(void* const* d_in, const int* in_sizes, int n_in,
                              void* d_out, int out_size) {
    const float* x  = (const float*)d_in[0];
    const float* wq = (const float*)d_in[1];
    const float* wk = (const float*)d_in[2];
    const float* wv = (const float*)d_in[3];
    const float* wo = (const float*)d_in[4];
    const float* ck = (const float*)d_in[5];
    const float* cv = (const float*)d_in[6];
    const float* fc = (const float*)d_in[7];
    const float* fs = (const float*)d_in[8];
    const int*   sp = (n_in > 9) ? (const int*)d_in[9] : nullptr;

    gemm_qkv_kernel<<<dim3(24, KSPLIT), 128>>>(x, wq, wk, wv);
    rope_combine_kernel<<<384, 256>>>(fc, fs);
    attn_split_kernel<<<dim3(N_KV, NSPLIT, BS), 256>>>(ck, cv, sp);
    combine_attn_kernel<<<dim3(N_HEADS, BS), 128>>>();
    gemm_wo_kernel<<<dim3(16, KSPLIT), 128>>>(wo);
    final_sum_kernel<<<512, 256>>>((float*)d_out);
}

// round 4
// speedup vs baseline: 2.0827x; 1.0262x over previous
#include <cuda_runtime.h>
#include <cuda_bf16.h>
#include <math.h>

// Problem constants
#define N_HEADS 32
#define N_KV 8
#define HDIM 128
#define DIM 4096
#define BS 32
#define MAXSEQ 2048
#define KSPLIT 32
#define NSPLIT 8   // KV splits for attention

// ---------------- device scratch (static, allocation-free) ----------------
__device__ float g_qkv_part[KSPLIT][BS][6144];
__device__ float g_q[BS * 4096];
__device__ float g_knew[BS * 1024];
__device__ float g_vnew[BS * 1024];
__device__ float g_po[BS * N_HEADS * NSPLIT * HDIM];
__device__ float g_pm[BS * N_HEADS * NSPLIT];
__device__ float g_pl[BS * N_HEADS * NSPLIT];
__device__ float g_attn[BS * 4096];
__device__ float g_wo_part[KSPLIT][BS * 4096];

#define XPAD 36   // smem row pitch for xs[k][b]

// packed dual-FMA: d = a * b + d on two fp32 lanes (one FFMA2 instruction)
__device__ __forceinline__ void fma2(unsigned long long& d,
                                     unsigned long long a,
                                     unsigned long long b) {
    asm("fma.rn.f32x2 %0, %1, %2, %0;" : "+l"(d) : "l"(a), "l"(b));
}
__device__ __forceinline__ unsigned long long bcast2(float v) {
    unsigned long long r;
    asm("mov.b64 %0, {%1, %1};" : "=l"(r) : "r"(__float_as_uint(v)));
    return r;
}

// ---------------- QKV GEMM: [32,4096] @ concat(wq,wk,wv) -> partials -----
// grid (24, 32 k-splits), block 128. 2 cols/thread, 32 batches in packed
// f32x2 accumulators. Weights prefetched 8-deep; x via broadcast LDS.128.
__global__ void __launch_bounds__(128)
gemm_qkv_kernel(const float* __restrict__ x,
                const float* __restrict__ wq,
                const float* __restrict__ wk,
                const float* __restrict__ wv) {
    __shared__ float xs[128 * XPAD];
    int tid = threadIdx.x;
    int gcol = (blockIdx.x * 128 + tid) * 2;
    const float* w; int ldw, c;
    if (gcol < 4096)      { w = wq; ldw = 4096; c = gcol; }
    else if (gcol < 5120) { w = wk; ldw = 1024; c = gcol - 4096; }
    else                  { w = wv; ldw = 1024; c = gcol - 5120; }
    int kbase = blockIdx.y * 128;

    {
        const float4* x4 = (const float4*)x;
        for (int u = tid; u < 32 * 32; u += 128) {
            int b = u & 31, k4 = u >> 5;
            float4 v = x4[b * 1024 + (kbase >> 2) + k4];
            xs[(k4 * 4 + 0) * XPAD + b] = v.x;
            xs[(k4 * 4 + 1) * XPAD + b] = v.y;
            xs[(k4 * 4 + 2) * XPAD + b] = v.z;
            xs[(k4 * 4 + 3) * XPAD + b] = v.w;
        }
    }
    __syncthreads();

    unsigned long long acc0[16], acc1[16];   // batch pairs (2i, 2i+1)
#pragma unroll
    for (int i = 0; i < 16; i++) { acc0[i] = 0ULL; acc1[i] = 0ULL; }

    const float* wp = w + (size_t)kbase * ldw + c;
    for (int kk = 0; kk < 128; kk += 8) {
        float2 wr[8];
#pragma unroll
        for (int j = 0; j < 8; j++)
            wr[j] = *(const float2*)(wp + (size_t)(kk + j) * ldw);
#pragma unroll
        for (int j = 0; j < 8; j++) {
            unsigned long long wx = bcast2(wr[j].x);
            unsigned long long wy = bcast2(wr[j].y);
            const float4* xrow = (const float4*)(xs + (kk + j) * XPAD);
#pragma unroll
            for (int b4 = 0; b4 < 8; b4++) {
                float4 xv = xrow[b4];                        // LDS.128 broadcast
                ulonglong2 xp = *reinterpret_cast<ulonglong2*>(&xv);
                fma2(acc0[b4*2+0], wx, xp.x);
                fma2(acc0[b4*2+1], wx, xp.y);
                fma2(acc1[b4*2+0], wy, xp.x);
                fma2(acc1[b4*2+1], wy, xp.y);
            }
        }
    }
    float* out = &g_qkv_part[blockIdx.y][0][0];
#pragma unroll
    for (int i = 0; i < 16; i++) {
        float2 a0 = *reinterpret_cast<float2*>(&acc0[i]);
        float2 a1 = *reinterpret_cast<float2*>(&acc1[i]);
        *(float2*)&out[(2*i  ) * 6144 + gcol] = make_float2(a0.x, a1.x);
        *(float2*)&out[(2*i+1) * 6144 + gcol] = make_float2(a0.y, a1.y);
    }
}

// ---------------- reduce K-split partials + RoPE -------------------------
__global__ void rope_combine_kernel(const float* __restrict__ fc,
                                    const float* __restrict__ fs) {
    int idx = blockIdx.x * blockDim.x + threadIdx.x;
    if (idx >= 32 * 3072) return;
    int b = idx / 3072;
    int col = (idx % 3072) * 2;
    float s0 = 0.f, s1 = 0.f;
#pragma unroll
    for (int p = 0; p < KSPLIT; p++) {
        s0 += g_qkv_part[p][b][col];
        s1 += g_qkv_part[p][b][col + 1];
    }
    if (col < 4096) {
        int i = (col & 127) >> 1;
        float cc = fc[i], ss = fs[i];
        g_q[b * 4096 + col]     = s0 * cc - s1 * ss;
        g_q[b * 4096 + col + 1] = s0 * ss + s1 * cc;
    } else if (col < 5120) {
        int kc = col - 4096;
        int i = (kc & 127) >> 1;
        float cc = fc[i], ss = fs[i];
        g_knew[b * 1024 + kc]     = s0 * cc - s1 * ss;
        g_knew[b * 1024 + kc + 1] = s0 * ss + s1 * cc;
    } else {
        int vc = col - 5120;
        g_vnew[b * 1024 + vc]     = s0;
        g_vnew[b * 1024 + vc + 1] = s1;
    }
}

// ---------------- split-KV attention -------------------------------------
// grid (8 kv-heads, 8 splits, 32 batches), block 256 (8 warps).
__global__ void __launch_bounds__(256)
attn_split_kernel(const float* __restrict__ cache_k,
                  const float* __restrict__ cache_v,
                  const int* __restrict__ sp) {
    __shared__ float qs[4 * 128];
    __shared__ float sc[4][256];
    __shared__ float vt[32 * 128];
    __shared__ float sm_m[4], sm_l[4];

    int g = blockIdx.x, split = blockIdx.y, b = blockIdx.z;
    int tid = threadIdx.x, lane = tid & 31, w = tid >> 5;
    int L = sp ? (sp[0] + 1) : MAXSEQ;
    int chunk = (L + NSPLIT - 1) / NSPLIT;
    int t0 = split * chunk;
    int cnt = L - t0;
    if (cnt > chunk) cnt = chunk;
    if (cnt < 0) cnt = 0;

    for (int u = tid; u < 512; u += 256)
        qs[u] = g_q[b * 4096 + g * 512 + u];
    __syncthreads();

    float4 qr[4];
#pragma unroll
    for (int h = 0; h < 4; h++) qr[h] = ((const float4*)qs)[h * 32 + lane];

    const float scale = 0.08838834764831845f;

    for (int ti = w; ti < cnt; ti += 8) {
        int t = t0 + ti;
        const float4* kp = (t == L - 1)
            ? (const float4*)(g_knew + b * 1024 + g * 128)
            : (const float4*)(cache_k + (((size_t)b * MAXSEQ + t) * N_KV + g) * HDIM);
        float4 kv = kp[lane];
        float a0 = qr[0].x*kv.x + qr[0].y*kv.y + qr[0].z*kv.z + qr[0].w*kv.w;
        float a1 = qr[1].x*kv.x + qr[1].y*kv.y + qr[1].z*kv.z + qr[1].w*kv.w;
        float a2 = qr[2].x*kv.x + qr[2].y*kv.y + qr[2].z*kv.z + qr[2].w*kv.w;
        float a3 = qr[3].x*kv.x + qr[3].y*kv.y + qr[3].z*kv.z + qr[3].w*kv.w;
#pragma unroll
        for (int off = 16; off; off >>= 1) {
            a0 += __shfl_xor_sync(~0u, a0, off);
            a1 += __shfl_xor_sync(~0u, a1, off);
            a2 += __shfl_xor_sync(~0u, a2, off);
            a3 += __shfl_xor_sync(~0u, a3, off);
        }
        if (lane == 0) {
            sc[0][ti] = a0 * scale; sc[1][ti] = a1 * scale;
            sc[2][ti] = a2 * scale; sc[3][ti] = a3 * scale;
        }
    }
    __syncthreads();

    if (w < 4) {
        float m = -1e30f;
        for (int ti = lane; ti < cnt; ti += 32) m = fmaxf(m, sc[w][ti]);
#pragma unroll
        for (int off = 16; off; off >>= 1) m = fmaxf(m, __shfl_xor_sync(~0u, m, off));
        float l = 0.f;
        for (int ti = lane; ti < cnt; ti += 32) {
            float e = __expf(sc[w][ti] - m);
            sc[w][ti] = e;
            l += e;
        }
#pragma unroll
        for (int off = 16; off; off >>= 1) l += __shfl_xor_sync(~0u, l, off);
        if (lane == 0) { sm_m[w] = m; sm_l[w] = l; }
    }
    __syncthreads();

    int h0 = tid >> 7;
    int d0 = tid & 127;
    int h1 = h0 + 2;
    float acc0 = 0.f, acc1 = 0.f;
    for (int tb = 0; tb < cnt; tb += 32) {
        int nt = cnt - tb; if (nt > 32) nt = 32;
        for (int u = tid; u < nt * 32; u += 256) {
            int r = u >> 5, c4 = u & 31;
            int t = t0 + tb + r;
            const float4* vp = (t == L - 1)
                ? (const float4*)(g_vnew + b * 1024 + g * 128)
                : (const float4*)(cache_v + (((size_t)b * MAXSEQ + t) * N_KV + g) * HDIM);
            ((float4*)vt)[r * 32 + c4] = vp[c4];
        }
        __syncthreads();
        for (int j = 0; j < nt; j++) {
            float vv = vt[j * 128 + d0];
            acc0 = fmaf(sc[h0][tb + j], vv, acc0);
            acc1 = fmaf(sc[h1][tb + j], vv, acc1);
        }
        __syncthreads();
    }

    int hh0 = g * 4 + h0, hh1 = g * 4 + h1;
    g_po[((b * N_HEADS + hh0) * NSPLIT + split) * HDIM + d0] = acc0;
    g_po[((b * N_HEADS + hh1) * NSPLIT + split) * HDIM + d0] = acc1;
    if (d0 == 0) {
        g_pm[(b * N_HEADS + hh0) * NSPLIT + split] = sm_m[h0];
        g_pl[(b * N_HEADS + hh0) * NSPLIT + split] = sm_l[h0];
        g_pm[(b * N_HEADS + hh1) * NSPLIT + split] = sm_m[h1];
        g_pl[(b * N_HEADS + hh1) * NSPLIT + split] = sm_l[h1];
    }
}

// ---------------- combine attention splits (log-sum-exp) -----------------
__global__ void combine_attn_kernel() {
    int h = blockIdx.x, b = blockIdx.y, d = threadIdx.x;
    int base = (b * N_HEADS + h) * NSPLIT;
    float M = -1e30f;
#pragma unroll
    for (int s = 0; s < NSPLIT; s++) M = fmaxf(M, g_pm[base + s]);
    float denom = 0.f, o = 0.f;
#pragma unroll
    for (int s = 0; s < NSPLIT; s++) {
        float wgt = __expf(g_pm[base + s] - M);
        denom += wgt * g_pl[base + s];
        o     += wgt * g_po[(base + s) * HDIM + d];
    }
    g_attn[b * 4096 + h * HDIM + d] = o / denom;
}

// ---------------- WO GEMM: g_attn[32,4096] @ wo[4096,4096] ---------------
__global__ void __launch_bounds__(128)
gemm_wo_kernel(const float* __restrict__ wo) {
    __shared__ float xs[128 * XPAD];
    int tid = threadIdx.x;
    int c = (blockIdx.x * 128 + tid) * 2;
    int kbase = blockIdx.y * 128;

    {
        const float4* x4 = (const float4*)g_attn;
        for (int u = tid; u < 32 * 32; u += 128) {
            int b = u & 31, k4 = u >> 5;
            float4 v = x4[b * 1024 + (kbase >> 2) + k4];
            xs[(k4 * 4 + 0) * XPAD + b] = v.x;
            xs[(k4 * 4 + 1) * XPAD + b] = v.y;
            xs[(k4 * 4 + 2) * XPAD + b] = v.z;
            xs[(k4 * 4 + 3) * XPAD + b] = v.w;
        }
    }
    __syncthreads();

    unsigned long long acc0[16], acc1[16];
#pragma unroll
    for (int i = 0; i < 16; i++) { acc0[i] = 0ULL; acc1[i] = 0ULL; }

    const float* wp = wo + (size_t)kbase * 4096 + c;
    for (int kk = 0; kk < 128; kk += 8) {
        float2 wr[8];
#pragma unroll
        for (int j = 0; j < 8; j++)
            wr[j] = *(const float2*)(wp + (size_t)(kk + j) * 4096);
#pragma unroll
        for (int j = 0; j < 8; j++) {
            unsigned long long wx = bcast2(wr[j].x);
            unsigned long long wy = bcast2(wr[j].y);
            const float4* xrow = (const float4*)(xs + (kk + j) * XPAD);
#pragma unroll
            for (int b4 = 0; b4 < 8; b4++) {
                float4 xv = xrow[b4];
                ulonglong2 xp = *reinterpret_cast<ulonglong2*>(&xv);
                fma2(acc0[b4*2+0], wx, xp.x);
                fma2(acc0[b4*2+1], wx, xp.y);
                fma2(acc1[b4*2+0], wy, xp.x);
                fma2(acc1[b4*2+1], wy, xp.y);
            }
        }
    }
    float* out = g_wo_part[blockIdx.y];
#pragma unroll
    for (int i = 0; i < 16; i++) {
        float2 a0 = *reinterpret_cast<float2*>(&acc0[i]);
        float2 a1 = *reinterpret_cast<float2*>(&acc1[i]);
        *(float2*)&out[(2*i  ) * 4096 + c] = make_float2(a0.x, a1.x);
        *(float2*)&out[(2*i+1) * 4096 + c] = make_float2(a0.y, a1.y);
    }
}

// ---------------- sum WO partials into d_out -----------------------------
__global__ void final_sum_kernel(float* __restrict__ out) {
    int idx = blockIdx.x * blockDim.x + threadIdx.x;
    float s = 0.f;
#pragma unroll
    for (int p = 0; p < KSPLIT; p++) s += g_wo_part[p][idx];
    out[idx] = s;
}

// ---------------- launch -------------------------------------------------
extern "C" void kernel_launch(void* const* d_in, const int* in_sizes, int n_in,
                              void* d_out, int out_size) {
    const float* x  = (const float*)d_in[0];
    const float* wq = (const float*)d_in[1];
    const float* wk = (const float*)d_in[2];
    const float* wv = (const float*)d_in[3];
    const float* wo = (const float*)d_in[4];
    const float* ck = (const float*)d_in[5];
    const float* cv = (const float*)d_in[6];
    const float* fc = (const float*)d_in[7];
    const float* fs = (const float*)d_in[8];
    const int*   sp = (n_in > 9) ? (const int*)d_in[9] : nullptr;

    gemm_qkv_kernel<<<dim3(24, KSPLIT), 128>>>(x, wq, wk, wv);
    rope_combine_kernel<<<384, 256>>>(fc, fs);
    attn_split_kernel<<<dim3(N_KV, NSPLIT, BS), 256>>>(ck, cv, sp);
    combine_attn_kernel<<<dim3(N_HEADS, BS), 128>>>();
    gemm_wo_kernel<<<dim3(16, KSPLIT), 128>>>(wo);
    final_sum_kernel<<<512, 256>>>((float*)d_out);
}